// round 15
// baseline (speedup 1.0000x reference)
#include <cuda_runtime.h>
#include <cuda_bf16.h>
#include <cstdint>
#include <math.h>

#define B_    2048
#define L_    30
#define D_    512
#define X_    512
#define H_    4
#define OUT_  512
#define ITER_ 4
#define ROWS_ (B_*L_)    /* 61440 */
#define NCHUNK_ 16       /* N-chunk partials: 8 y-blocks x 2 warp halves */

// scratch (device globals: no allocation allowed)
__device__ float g_Q[B_*OUT_];                  // 4 MB : left @ W1_left^T
__device__ float g_linpart[NCHUNK_*ROWS_*H_];   // 15.7 MB : per-N-chunk partial lin

// ===========================================================================
// helpers
// ===========================================================================
static __device__ __forceinline__ uint32_t bf16_bits(__nv_bfloat16 h) {
    return (uint32_t)*(const unsigned short*)&h;
}

// split-convert float4 (4 consecutive k) into packed hi (uint2) + lo (uint2);
// low 16 bits of each uint = lower k index.
static __device__ __forceinline__ void split4(float4 v, uint2& hi, uint2& lo) {
    __nv_bfloat16 h0 = __float2bfloat16_rn(v.x);
    __nv_bfloat16 h1 = __float2bfloat16_rn(v.y);
    __nv_bfloat16 h2 = __float2bfloat16_rn(v.z);
    __nv_bfloat16 h3 = __float2bfloat16_rn(v.w);
    __nv_bfloat16 l0 = __float2bfloat16_rn(v.x - __bfloat162float(h0));
    __nv_bfloat16 l1 = __float2bfloat16_rn(v.y - __bfloat162float(h1));
    __nv_bfloat16 l2 = __float2bfloat16_rn(v.z - __bfloat162float(h2));
    __nv_bfloat16 l3 = __float2bfloat16_rn(v.w - __bfloat162float(h3));
    hi.x = bf16_bits(h0) | (bf16_bits(h1) << 16);
    hi.y = bf16_bits(h2) | (bf16_bits(h3) << 16);
    lo.x = bf16_bits(l0) | (bf16_bits(l1) << 16);
    lo.y = bf16_bits(l2) | (bf16_bits(l3) << 16);
}

// m16n8k16 bf16 MMA, fp32 accumulate in place. Base sm_80+ instruction —
// compiles for plain .target sm_103 (no arch-suffix features).
static __device__ __forceinline__ void mma_bf16(float* d, const uint32_t* a,
                                                const uint32_t* b) {
    asm volatile(
        "mma.sync.aligned.m16n8k16.row.col.f32.bf16.bf16.f32 "
        "{%0,%1,%2,%3}, {%4,%5,%6,%7}, {%8,%9}, {%0,%1,%2,%3};"
        : "+f"(d[0]), "+f"(d[1]), "+f"(d[2]), "+f"(d[3])
        : "r"(a[0]), "r"(a[1]), "r"(a[2]), "r"(a[3]), "r"(b[0]), "r"(b[1]));
}

// ---------------------------------------------------------------------------
// K1: Q[b,o] = sum_c left[b,c] * W1[o,c]   (2048 x 512 x 512) — FFMA (small)
// ---------------------------------------------------------------------------
__global__ void __launch_bounds__(256) k1_qgemm(const float* __restrict__ A,
                                                const float* __restrict__ W1)
{
    __shared__ float As[16][64];
    __shared__ float Bs[16][64];
    int tid = threadIdx.x;
    int tx = tid & 15, ty = tid >> 4;
    int m0 = blockIdx.x * 64, n0 = blockIdx.y * 64;
    float acc[4][4] = {};
    for (int k0 = 0; k0 < 512; k0 += 16) {
        int r  = tid >> 2;
        int kq = (tid & 3) * 4;
        float4 v = *(const float4*)&A [(m0 + r) * 512  + k0 + kq];
        As[kq+0][r]=v.x; As[kq+1][r]=v.y; As[kq+2][r]=v.z; As[kq+3][r]=v.w;
        float4 w = *(const float4*)&W1[(n0 + r) * 1024 + k0 + kq];
        Bs[kq+0][r]=w.x; Bs[kq+1][r]=w.y; Bs[kq+2][r]=w.z; Bs[kq+3][r]=w.w;
        __syncthreads();
        #pragma unroll
        for (int kk = 0; kk < 16; kk++) {
            float a[4], b[4];
            #pragma unroll
            for (int i = 0; i < 4; i++) a[i] = As[kk][ty*4 + i];
            #pragma unroll
            for (int j = 0; j < 4; j++) b[j] = Bs[kk][tx*4 + j];
            #pragma unroll
            for (int i = 0; i < 4; i++)
                #pragma unroll
                for (int j = 0; j < 4; j++)
                    acc[i][j] += a[i] * b[j];
        }
        __syncthreads();
    }
    #pragma unroll
    for (int i = 0; i < 4; i++)
        #pragma unroll
        for (int j = 0; j < 4; j++)
            g_Q[(m0 + ty*4 + i)*512 + n0 + tx*4 + j] = acc[i][j];
}

// ---------------------------------------------------------------------------
// K2 (mma.sync bf16 split): P = right @ W1right^T, fused epilogue:
//   t = tanh(P + Q[b]);  linpart[ci][row][h] = sum_{o in 32-col slice} t*W2[h,o]
// grid (480, 8), 256 threads = 8 warps (4 M x 2 N). CTA tile 128 x 64.
// K chunks of 32; A/B split to bf16 hi/lo in smem (K-stride 18 uints, padded).
// 3-term MMA: hi*hi + hi*lo + lo*hi, fp32 register accumulators.
// ---------------------------------------------------------------------------
__global__ void __launch_bounds__(256) k2_mma(const float* __restrict__ A,
                                              const float* __restrict__ W1,
                                              const float* __restrict__ W2)
{
    __shared__ __align__(16) uint32_t sAh[128*18];
    __shared__ __align__(16) uint32_t sAl[128*18];
    __shared__ __align__(16) uint32_t sBh[64*18];
    __shared__ __align__(16) uint32_t sBl[64*18];

    const int tid  = threadIdx.x;
    const int wid  = tid >> 5, lane = tid & 31;
    const int g    = lane >> 2, t4 = lane & 3;     // groupID / thread-in-group
    const int wm   = wid >> 1,  wn = wid & 1;      // warp M/N position
    const int m0   = blockIdx.x * 128, n0 = blockIdx.y * 64;

    float acc[2][4][4];
    #pragma unroll
    for (int mt = 0; mt < 2; mt++)
        #pragma unroll
        for (int nt = 0; nt < 4; nt++)
            #pragma unroll
            for (int r = 0; r < 4; r++) acc[mt][nt][r] = 0.f;

    for (int c = 0; c < 16; c++) {
        const int k0 = c * 32;
        // A chunk: 128 rows x 32 k (8 float4 per row)
        for (int e = tid; e < 128*8; e += 256) {
            int r = e >> 3, q = (e & 7) * 4;
            float4 v = *(const float4*)&A[(size_t)(m0 + r)*512 + k0 + q];
            uint2 hi, lo; split4(v, hi, lo);
            int idx = r*18 + (q >> 1);
            sAh[idx] = hi.x; sAh[idx+1] = hi.y;
            sAl[idx] = lo.x; sAl[idx+1] = lo.y;
        }
        // B chunk: 64 n-rows x 32 k from W1 right half
        for (int e = tid; e < 64*8; e += 256) {
            int r = e >> 3, q = (e & 7) * 4;
            float4 v = *(const float4*)&W1[(size_t)(n0 + r)*1024 + 512 + k0 + q];
            uint2 hi, lo; split4(v, hi, lo);
            int idx = r*18 + (q >> 1);
            sBh[idx] = hi.x; sBh[idx+1] = hi.y;
            sBl[idx] = lo.x; sBl[idx+1] = lo.y;
        }
        __syncthreads();

        #pragma unroll
        for (int ks = 0; ks < 2; ks++) {
            const int i0 = (ks*16 + 2*t4) >> 1;       // uint index, k-lo
            const int i1 = (ks*16 + 8 + 2*t4) >> 1;   // uint index, k-hi
            uint32_t ah[2][4], al[2][4];
            #pragma unroll
            for (int mt = 0; mt < 2; mt++) {
                int r0 = (wm*32 + mt*16 + g) * 18;
                int r8 = r0 + 8*18;
                ah[mt][0] = sAh[r0 + i0]; ah[mt][1] = sAh[r8 + i0];
                ah[mt][2] = sAh[r0 + i1]; ah[mt][3] = sAh[r8 + i1];
                al[mt][0] = sAl[r0 + i0]; al[mt][1] = sAl[r8 + i0];
                al[mt][2] = sAl[r0 + i1]; al[mt][3] = sAl[r8 + i1];
            }
            uint32_t bh[4][2], bl[4][2];
            #pragma unroll
            for (int nt = 0; nt < 4; nt++) {
                int nb = (wn*32 + nt*8 + g) * 18;
                bh[nt][0] = sBh[nb + i0]; bh[nt][1] = sBh[nb + i1];
                bl[nt][0] = sBl[nb + i0]; bl[nt][1] = sBl[nb + i1];
            }
            #pragma unroll
            for (int mt = 0; mt < 2; mt++)
                #pragma unroll
                for (int nt = 0; nt < 4; nt++) {
                    mma_bf16(acc[mt][nt], ah[mt], bh[nt]);
                    mma_bf16(acc[mt][nt], ah[mt], bl[nt]);
                    mma_bf16(acc[mt][nt], al[mt], bh[nt]);
                }
        }
        __syncthreads();
    }

    // ---- fused epilogue: tanh(P+Q), reduce 32 cols into H=4 per row
    // D frag: c0=(g,2t), c1=(g,2t+1), c2=(g+8,2t), c3=(g+8,2t+1)
    const int ci = blockIdx.y * 2 + wn;      // 16 N-chunks of 32 cols
    float psA[2][4] = {}, psB[2][4] = {};
    #pragma unroll
    for (int mt = 0; mt < 2; mt++) {
        int rowA = m0 + wm*32 + mt*16 + g;
        int rowB = rowA + 8;
        const float* qA = &g_Q[(size_t)(rowA / L_) * 512];
        const float* qB = &g_Q[(size_t)(rowB / L_) * 512];
        #pragma unroll
        for (int nt = 0; nt < 4; nt++) {
            int col0 = n0 + wn*32 + nt*8 + 2*t4;
            float tA0 = tanhf(acc[mt][nt][0] + qA[col0]);
            float tA1 = tanhf(acc[mt][nt][1] + qA[col0+1]);
            float tB0 = tanhf(acc[mt][nt][2] + qB[col0]);
            float tB1 = tanhf(acc[mt][nt][3] + qB[col0+1]);
            #pragma unroll
            for (int h = 0; h < 4; h++) {
                float w0 = W2[h*512 + col0], w1 = W2[h*512 + col0 + 1];
                psA[mt][h] += tA0 * w0 + tA1 * w1;
                psB[mt][h] += tB0 * w0 + tB1 * w1;
            }
        }
    }
    // reduce across the 4 lanes of each tig group (lane bits 0-1)
    #pragma unroll
    for (int mt = 0; mt < 2; mt++)
        #pragma unroll
        for (int h = 0; h < 4; h++) {
            psA[mt][h] += __shfl_xor_sync(0xffffffffu, psA[mt][h], 1);
            psA[mt][h] += __shfl_xor_sync(0xffffffffu, psA[mt][h], 2);
            psB[mt][h] += __shfl_xor_sync(0xffffffffu, psB[mt][h], 1);
            psB[mt][h] += __shfl_xor_sync(0xffffffffu, psB[mt][h], 2);
        }
    if (t4 == 0) {
        #pragma unroll
        for (int mt = 0; mt < 2; mt++) {
            int rowA = m0 + wm*32 + mt*16 + g;
            #pragma unroll
            for (int h = 0; h < 4; h++) {
                g_linpart[((size_t)ci*ROWS_ + rowA)*4 + h]     = psA[mt][h];
                g_linpart[((size_t)ci*ROWS_ + rowA + 8)*4 + h] = psB[mt][h];
            }
        }
    }
}

// ---------------------------------------------------------------------------
// K3: per-batch fused — Gram matrix, credibility chain, softmax, AOA, attended
// grid = 2048 blocks x 256 threads, dynamic smem ~72 KB
// ---------------------------------------------------------------------------
__global__ void k3_fused(const float* __restrict__ right,
                         const int*   __restrict__ mask,
                         const float* __restrict__ W_o,
                         const float* __restrict__ b_o,
                         const float* __restrict__ scales_blk,
                         const float* __restrict__ W_c,
                         const float* __restrict__ b_c,
                         const float* __restrict__ scale_fin,
                         const float* __restrict__ W_aoa,
                         const float* __restrict__ b_aoa,
                         float* __restrict__ out)
{
    extern __shared__ float sm[];
    float* rsm  = sm;                 // 32 rows x 516 pitch (rows 30,31 zero)
    float* G    = rsm + 32*516;       // 32x32
    float* Xb   = G    + 1024;        // 32
    float* cred = Xb   + 32;          // 32
    float* lin  = cred + 32;          // 30x4
    float* aw   = lin  + 128;         // 30x4
    float* evd  = aw   + 128;         // 30x4
    float* aw2  = evd  + 128;         // 30x4
    int*   ish  = (int*)(aw2 + 128);  // [0] = valid length

    const int b   = blockIdx.x;
    const int tid = threadIdx.x;
    const float inv_sqrt_d = 0.044194173824159216f;   // 1/sqrt(512)

    {
        const float4* src = (const float4*)&right[(size_t)b * (L_*D_)];
        for (int f = tid; f < 30*128; f += 256) {
            int r = f >> 7, c4 = f & 127;
            *(float4*)&rsm[r*516 + c4*4] = src[f];
        }
        for (int f = tid; f < 2*128; f += 256) {
            int r = 30 + (f >> 7), c4 = f & 127;
            *(float4*)&rsm[r*516 + c4*4] = make_float4(0.f,0.f,0.f,0.f);
        }
        if (tid == 0) {
            int len = 0;
            for (int l = 0; l < L_; l++) len += mask[b*L_ + l];
            ish[0] = len;
        }
    }
    __syncthreads();

    // Gram matrix G = R R^T : 64 threads, 4x4 register tiles
    if (tid < 64) {
        int q0 = (tid >> 3) * 4, k0 = (tid & 7) * 4;
        float acc[4][4] = {};
        for (int c4 = 0; c4 < 128; c4++) {
            float4 a[4], bb[4];
            #pragma unroll
            for (int i = 0; i < 4; i++) a[i]  = *(const float4*)&rsm[(q0+i)*516 + c4*4];
            #pragma unroll
            for (int j = 0; j < 4; j++) bb[j] = *(const float4*)&rsm[(k0+j)*516 + c4*4];
            #pragma unroll
            for (int i = 0; i < 4; i++)
                #pragma unroll
                for (int j = 0; j < 4; j++)
                    acc[i][j] += a[i].x*bb[j].x + a[i].y*bb[j].y
                               + a[i].z*bb[j].z + a[i].w*bb[j].w;
        }
        #pragma unroll
        for (int i = 0; i < 4; i++)
            #pragma unroll
            for (int j = 0; j < 4; j++)
                G[(q0+i)*32 + k0+j] = acc[i][j];
    }
    __syncthreads();

    // credibility chain (keyt = Xb .* right  =>  scores_i = G .* Xb)
    if (tid < 32) {
        int q = tid;
        int   len   = ish[0];
        float len_f = (float)len;
        Xb[q] = (q < 30) ? 1.0f : 0.0f;
        __syncwarp();
        for (int it = 0; it < ITER_; it++) {
            float sc = inv_sqrt_d * scales_blk[it];
            if (q < 30) {
                float cr = 0.f;
                for (int k = 0; k < len; k++) cr += G[q*32 + k] * Xb[k];
                cred[q] = cr * sc / len_f;
            }
            __syncwarp();
            float xb = 0.f;
            if (q < 30) {
                float y = b_o[it*L_ + q];
                for (int j = 0; j < 30; j++) y += W_o[it*900 + q*30 + j] * cred[j];
                xb = tanhf(expf(y));
            }
            __syncwarp();
            if (q < 30) Xb[q] = xb;
            __syncwarp();
        }
        if (q < 30) {
            float sc = inv_sqrt_d * scale_fin[0];
            float e0 = b_c[0], e1 = b_c[1], e2 = b_c[2], e3 = b_c[3];
            for (int k = 0; k < 30; k++) {
                float s = G[q*32 + k] * Xb[k] * sc;
                e0 += s * W_c[k]; e1 += s * W_c[30+k]; e2 += s * W_c[60+k]; e3 += s * W_c[90+k];
            }
            evd[q*4+0] = tanhf(expf(e0)); evd[q*4+1] = tanhf(expf(e1));
            evd[q*4+2] = tanhf(expf(e2)); evd[q*4+3] = tanhf(expf(e3));
        }
    }
    __syncthreads();

    // lin = sum of 16 N-chunk partials, masked
    if (tid < 120) {
        int l = tid >> 2, h = tid & 3;
        int row = b*L_ + l;
        float s = 0.f;
        #pragma unroll
        for (int c = 0; c < NCHUNK_; c++)
            s += g_linpart[((size_t)c*ROWS_ + row)*4 + h];
        if (mask[row] == 0) s = -INFINITY;
        lin[l*4 + h] = s;
    }
    __syncthreads();

    // softmax over l (per h)
    if (tid < 4) {
        int h = tid;
        float m = -INFINITY;
        for (int l = 0; l < 30; l++) m = fmaxf(m, lin[l*4 + h]);
        float ssum = 0.f;
        for (int l = 0; l < 30; l++) { float e = expf(lin[l*4+h] - m); aw[l*4+h] = e; ssum += e; }
        float r = 1.f / ssum;
        for (int l = 0; l < 30; l++) aw[l*4 + h] *= r;
    }
    __syncthreads();

    // AOA GLU + write out2 = [evd | aw2]
    if (tid < 30) {
        int l = tid;
        float cat[8];
        #pragma unroll
        for (int h = 0; h < 4; h++) { cat[h] = aw[l*4+h]; cat[4+h] = evd[l*4+h]; }
        float g8[8];
        #pragma unroll
        for (int j = 0; j < 8; j++) {
            float s = b_aoa[j];
            #pragma unroll
            for (int m2 = 0; m2 < 8; m2++) s += W_aoa[j*8 + m2] * cat[m2];
            g8[j] = s;
        }
        size_t o2 = (size_t)B_*D_*H_ + (size_t)b*L_*8 + (size_t)l*8;
        #pragma unroll
        for (int h = 0; h < 4; h++) {
            float a2 = g8[h] * (1.f / (1.f + expf(-g8[4+h])));
            aw2[l*4 + h] = a2;
            out[o2 + h]     = evd[l*4 + h];
            out[o2 + 4 + h] = a2;
        }
    }
    __syncthreads();

    // attended[b,d,h] = sum_l right[b,l,d] * aw2[l,h]
    for (int d = tid; d < 512; d += 256) {
        float a0 = 0.f, a1 = 0.f, a2 = 0.f, a3 = 0.f;
        for (int l = 0; l < 30; l++) {
            float r = rsm[l*516 + d];
            a0 += r * aw2[l*4+0]; a1 += r * aw2[l*4+1];
            a2 += r * aw2[l*4+2]; a3 += r * aw2[l*4+3];
        }
        size_t o1 = (size_t)b*D_*H_ + (size_t)d*H_;
        out[o1+0] = a0; out[o1+1] = a1; out[o1+2] = a2; out[o1+3] = a3;
    }
}

// ---------------------------------------------------------------------------
extern "C" void kernel_launch(void* const* d_in, const int* in_sizes, int n_in,
                              void* d_out, int out_size)
{
    const float* left   = (const float*)d_in[0];
    const float* right  = (const float*)d_in[1];
    const int*   mask   = (const int*)  d_in[2];
    const float* W1     = (const float*)d_in[3];
    const float* W2     = (const float*)d_in[4];
    const float* W_o    = (const float*)d_in[5];
    const float* b_o    = (const float*)d_in[6];
    const float* scales = (const float*)d_in[7];
    const float* W_c    = (const float*)d_in[8];
    const float* b_c    = (const float*)d_in[9];
    const float* s_fin  = (const float*)d_in[10];
    const float* W_aoa  = (const float*)d_in[11];
    const float* b_aoa  = (const float*)d_in[12];
    float* out = (float*)d_out;

    const int smem3 = (32*516 + 1024 + 32 + 32 + 4*128 + 8) * (int)sizeof(float);
    cudaFuncSetAttribute(k3_fused, cudaFuncAttributeMaxDynamicSharedMemorySize, smem3);

    dim3 g1(2048/64, 512/64);      // 32 x 8
    k1_qgemm<<<g1, 256>>>(left, W1);

    dim3 g2(ROWS_/128, 512/64);    // 480 x 8
    k2_mma<<<g2, 256>>>(right, W1, W2);

    k3_fused<<<B_, 256, smem3>>>(right, mask, W_o, b_o, scales,
                                 W_c, b_c, s_fin, W_aoa, b_aoa, out);
}

// round 16
// speedup vs baseline: 1.3645x; 1.3645x over previous
#include <cuda_runtime.h>
#include <cuda_bf16.h>
#include <cstdint>
#include <math.h>

#define B_    2048
#define L_    30
#define D_    512
#define X_    512
#define H_    4
#define OUT_  512
#define ITER_ 4
#define ROWS_ (B_*L_)    /* 61440 */
#define NCHUNK_ 16       /* N-chunk partials: 8 y-blocks x 2 warp halves */

// scratch (device globals: no allocation allowed)
__device__ float    g_Q[B_*OUT_];                  // 4 MB
__device__ float    g_linpart[NCHUNK_*ROWS_*H_];   // 15.7 MB
__device__ uint32_t g_Ah[(size_t)ROWS_*256];       // 63 MB : right hi (k-pair packed)
__device__ uint32_t g_Al[(size_t)ROWS_*256];       // 63 MB : right lo
__device__ uint32_t g_Bh[512*256];                 // 0.5 MB: W1-right hi
__device__ uint32_t g_Bl[512*256];                 // 0.5 MB: W1-right lo

// ===========================================================================
// helpers
// ===========================================================================
static __device__ __forceinline__ uint32_t bf16_bits(__nv_bfloat16 h) {
    return (uint32_t)*(const unsigned short*)&h;
}

// split-convert float4 (4 consecutive k) into packed hi (uint2) + lo (uint2);
// low 16 bits of each uint = lower k index.
static __device__ __forceinline__ void split4(float4 v, uint2& hi, uint2& lo) {
    __nv_bfloat16 h0 = __float2bfloat16_rn(v.x);
    __nv_bfloat16 h1 = __float2bfloat16_rn(v.y);
    __nv_bfloat16 h2 = __float2bfloat16_rn(v.z);
    __nv_bfloat16 h3 = __float2bfloat16_rn(v.w);
    __nv_bfloat16 l0 = __float2bfloat16_rn(v.x - __bfloat162float(h0));
    __nv_bfloat16 l1 = __float2bfloat16_rn(v.y - __bfloat162float(h1));
    __nv_bfloat16 l2 = __float2bfloat16_rn(v.z - __bfloat162float(h2));
    __nv_bfloat16 l3 = __float2bfloat16_rn(v.w - __bfloat162float(h3));
    hi.x = bf16_bits(h0) | (bf16_bits(h1) << 16);
    hi.y = bf16_bits(h2) | (bf16_bits(h3) << 16);
    lo.x = bf16_bits(l0) | (bf16_bits(l1) << 16);
    lo.y = bf16_bits(l2) | (bf16_bits(l3) << 16);
}

// m16n8k16 bf16 MMA, fp32 accumulate in place (base sm_80+ instruction).
static __device__ __forceinline__ void mma_bf16(float* d, const uint32_t* a,
                                                const uint32_t* b) {
    asm volatile(
        "mma.sync.aligned.m16n8k16.row.col.f32.bf16.bf16.f32 "
        "{%0,%1,%2,%3}, {%4,%5,%6,%7}, {%8,%9}, {%0,%1,%2,%3};"
        : "+f"(d[0]), "+f"(d[1]), "+f"(d[2]), "+f"(d[3])
        : "r"(a[0]), "r"(a[1]), "r"(a[2]), "r"(a[3]), "r"(b[0]), "r"(b[1]));
}

// ---------------------------------------------------------------------------
// K0: pre-convert fp32 -> bf16 hi/lo, k-pair packed (uint = bf16(k)|bf16(k+1)<<16)
// dst row stride = cols4*2 uints.
// ---------------------------------------------------------------------------
__global__ void __launch_bounds__(256) k0_convert(const float* __restrict__ src,
                                                  int rowStride, int colOff, int cols4,
                                                  long total4,
                                                  uint32_t* __restrict__ dstH,
                                                  uint32_t* __restrict__ dstL)
{
    long i = (long)blockIdx.x * 256 + threadIdx.x;
    if (i >= total4) return;
    int r  = (int)(i / cols4);
    int c4 = (int)(i - (long)r * cols4);
    float4 v = *(const float4*)&src[(size_t)r*rowStride + colOff + c4*4];
    uint2 hi, lo; split4(v, hi, lo);
    size_t o = (size_t)r*(cols4*2) + c4*2;
    *(uint2*)&dstH[o] = hi;
    *(uint2*)&dstL[o] = lo;
}

// ---------------------------------------------------------------------------
// K1: Q[b,o] = sum_c left[b,c] * W1[o,c]   (2048 x 512 x 512) — FFMA (small)
// ---------------------------------------------------------------------------
__global__ void __launch_bounds__(256) k1_qgemm(const float* __restrict__ A,
                                                const float* __restrict__ W1)
{
    __shared__ float As[16][64];
    __shared__ float Bs[16][64];
    int tid = threadIdx.x;
    int tx = tid & 15, ty = tid >> 4;
    int m0 = blockIdx.x * 64, n0 = blockIdx.y * 64;
    float acc[4][4] = {};
    for (int k0 = 0; k0 < 512; k0 += 16) {
        int r  = tid >> 2;
        int kq = (tid & 3) * 4;
        float4 v = *(const float4*)&A [(m0 + r) * 512  + k0 + kq];
        As[kq+0][r]=v.x; As[kq+1][r]=v.y; As[kq+2][r]=v.z; As[kq+3][r]=v.w;
        float4 w = *(const float4*)&W1[(n0 + r) * 1024 + k0 + kq];
        Bs[kq+0][r]=w.x; Bs[kq+1][r]=w.y; Bs[kq+2][r]=w.z; Bs[kq+3][r]=w.w;
        __syncthreads();
        #pragma unroll
        for (int kk = 0; kk < 16; kk++) {
            float a[4], b[4];
            #pragma unroll
            for (int i = 0; i < 4; i++) a[i] = As[kk][ty*4 + i];
            #pragma unroll
            for (int j = 0; j < 4; j++) b[j] = Bs[kk][tx*4 + j];
            #pragma unroll
            for (int i = 0; i < 4; i++)
                #pragma unroll
                for (int j = 0; j < 4; j++)
                    acc[i][j] += a[i] * b[j];
        }
        __syncthreads();
    }
    #pragma unroll
    for (int i = 0; i < 4; i++)
        #pragma unroll
        for (int j = 0; j < 4; j++)
            g_Q[(m0 + ty*4 + i)*512 + n0 + tx*4 + j] = acc[i][j];
}

// ---------------------------------------------------------------------------
// K2 (mma.sync bf16 split, preconverted operands): P = right @ W1right^T,
// fused epilogue into g_linpart. grid (480, 8), 256 thr = 8 warps (4M x 2N).
// CTA tile 128x64, K chunks of 32. Smem row stride 20 uints (16B-aligned
// STS.128; fragment rows conflict-free: 20g mod 32 distinct for g in [0,8)).
// ---------------------------------------------------------------------------
__global__ void __launch_bounds__(256) k2_mma(const float* __restrict__ W2)
{
    __shared__ __align__(16) uint32_t sAh[128*20];
    __shared__ __align__(16) uint32_t sAl[128*20];
    __shared__ __align__(16) uint32_t sBh[64*20];
    __shared__ __align__(16) uint32_t sBl[64*20];

    const int tid  = threadIdx.x;
    const int wid  = tid >> 5, lane = tid & 31;
    const int g    = lane >> 2, t4 = lane & 3;
    const int wm   = wid >> 1,  wn = wid & 1;
    const int m0   = blockIdx.x * 128, n0 = blockIdx.y * 64;

    float acc[2][4][4];
    #pragma unroll
    for (int mt = 0; mt < 2; mt++)
        #pragma unroll
        for (int nt = 0; nt < 4; nt++)
            #pragma unroll
            for (int r = 0; r < 4; r++) acc[mt][nt][r] = 0.f;

    for (int c = 0; c < 16; c++) {
        // A: 128 rows x 16 uints (4 x uint4 per row)
        #pragma unroll
        for (int e = tid; e < 128*4; e += 256) {
            int r = e >> 2, j = e & 3;
            size_t go = (size_t)(m0 + r)*256 + c*16 + j*4;
            *(uint4*)&sAh[r*20 + j*4] = *(const uint4*)&g_Ah[go];
            *(uint4*)&sAl[r*20 + j*4] = *(const uint4*)&g_Al[go];
        }
        // B: 64 rows x 16 uints
        #pragma unroll
        for (int e = tid; e < 64*4; e += 256) {
            int r = e >> 2, j = e & 3;
            size_t go = (size_t)(n0 + r)*256 + c*16 + j*4;
            *(uint4*)&sBh[r*20 + j*4] = *(const uint4*)&g_Bh[go];
            *(uint4*)&sBl[r*20 + j*4] = *(const uint4*)&g_Bl[go];
        }
        __syncthreads();

        #pragma unroll
        for (int ks = 0; ks < 2; ks++) {
            const int i0 = ks*8 + t4;
            const int i1 = i0 + 4;
            uint32_t ah[2][4], al[2][4];
            #pragma unroll
            for (int mt = 0; mt < 2; mt++) {
                int r0 = (wm*32 + mt*16 + g) * 20;
                int r8 = r0 + 8*20;
                ah[mt][0] = sAh[r0 + i0]; ah[mt][1] = sAh[r8 + i0];
                ah[mt][2] = sAh[r0 + i1]; ah[mt][3] = sAh[r8 + i1];
                al[mt][0] = sAl[r0 + i0]; al[mt][1] = sAl[r8 + i0];
                al[mt][2] = sAl[r0 + i1]; al[mt][3] = sAl[r8 + i1];
            }
            uint32_t bh[4][2], bl[4][2];
            #pragma unroll
            for (int nt = 0; nt < 4; nt++) {
                int nb = (wn*32 + nt*8 + g) * 20;
                bh[nt][0] = sBh[nb + i0]; bh[nt][1] = sBh[nb + i1];
                bl[nt][0] = sBl[nb + i0]; bl[nt][1] = sBl[nb + i1];
            }
            #pragma unroll
            for (int mt = 0; mt < 2; mt++)
                #pragma unroll
                for (int nt = 0; nt < 4; nt++) {
                    mma_bf16(acc[mt][nt], ah[mt], bh[nt]);
                    mma_bf16(acc[mt][nt], ah[mt], bl[nt]);
                    mma_bf16(acc[mt][nt], al[mt], bh[nt]);
                }
        }
        __syncthreads();
    }

    // ---- fused epilogue: tanh(P+Q), reduce 32 cols into H=4 per row
    const int ci = blockIdx.y * 2 + wn;
    float psA[2][4] = {}, psB[2][4] = {};
    #pragma unroll
    for (int mt = 0; mt < 2; mt++) {
        int rowA = m0 + wm*32 + mt*16 + g;
        int rowB = rowA + 8;
        const float* qA = &g_Q[(size_t)(rowA / L_) * 512];
        const float* qB = &g_Q[(size_t)(rowB / L_) * 512];
        #pragma unroll
        for (int nt = 0; nt < 4; nt++) {
            int col0 = n0 + wn*32 + nt*8 + 2*t4;
            float tA0 = tanhf(acc[mt][nt][0] + qA[col0]);
            float tA1 = tanhf(acc[mt][nt][1] + qA[col0+1]);
            float tB0 = tanhf(acc[mt][nt][2] + qB[col0]);
            float tB1 = tanhf(acc[mt][nt][3] + qB[col0+1]);
            #pragma unroll
            for (int h = 0; h < 4; h++) {
                float w0 = W2[h*512 + col0], w1 = W2[h*512 + col0 + 1];
                psA[mt][h] += tA0 * w0 + tA1 * w1;
                psB[mt][h] += tB0 * w0 + tB1 * w1;
            }
        }
    }
    #pragma unroll
    for (int mt = 0; mt < 2; mt++)
        #pragma unroll
        for (int h = 0; h < 4; h++) {
            psA[mt][h] += __shfl_xor_sync(0xffffffffu, psA[mt][h], 1);
            psA[mt][h] += __shfl_xor_sync(0xffffffffu, psA[mt][h], 2);
            psB[mt][h] += __shfl_xor_sync(0xffffffffu, psB[mt][h], 1);
            psB[mt][h] += __shfl_xor_sync(0xffffffffu, psB[mt][h], 2);
        }
    if (t4 == 0) {
        #pragma unroll
        for (int mt = 0; mt < 2; mt++) {
            int rowA = m0 + wm*32 + mt*16 + g;
            #pragma unroll
            for (int h = 0; h < 4; h++) {
                g_linpart[((size_t)ci*ROWS_ + rowA)*4 + h]     = psA[mt][h];
                g_linpart[((size_t)ci*ROWS_ + rowA + 8)*4 + h] = psB[mt][h];
            }
        }
    }
}

// ---------------------------------------------------------------------------
// K3: per-batch fused — Gram (K-split x4 over 256 threads), credibility chain,
// softmax, AOA, attended. grid 2048 x 256 threads, ~89 KB dynamic smem.
// ---------------------------------------------------------------------------
__global__ void k3_fused(const float* __restrict__ right,
                         const int*   __restrict__ mask,
                         const float* __restrict__ W_o,
                         const float* __restrict__ b_o,
                         const float* __restrict__ scales_blk,
                         const float* __restrict__ W_c,
                         const float* __restrict__ b_c,
                         const float* __restrict__ scale_fin,
                         const float* __restrict__ W_aoa,
                         const float* __restrict__ b_aoa,
                         float* __restrict__ out)
{
    extern __shared__ float sm[];
    float* rsm  = sm;                 // 32 x 516 pitch (rows 30,31 zero)
    float* Gp   = rsm + 32*516;       // 4 x 32 x 32 partials
    float* G    = Gp  + 4096;         // 32x32
    float* Xb   = G   + 1024;         // 32
    float* cred = Xb  + 32;           // 32
    float* lin  = cred + 32;          // 30x4
    float* aw   = lin  + 128;         // 30x4
    float* evd  = aw   + 128;         // 30x4
    float* aw2  = evd  + 128;         // 30x4
    int*   ish  = (int*)(aw2 + 128);  // [0] = valid length

    const int b   = blockIdx.x;
    const int tid = threadIdx.x;
    const float inv_sqrt_d = 0.044194173824159216f;   // 1/sqrt(512)

    {
        const float4* src = (const float4*)&right[(size_t)b * (L_*D_)];
        for (int f = tid; f < 30*128; f += 256) {
            int r = f >> 7, c4 = f & 127;
            *(float4*)&rsm[r*516 + c4*4] = src[f];
        }
        for (int f = tid; f < 2*128; f += 256) {
            int r = 30 + (f >> 7), c4 = f & 127;
            *(float4*)&rsm[r*516 + c4*4] = make_float4(0.f,0.f,0.f,0.f);
        }
        if (tid == 0) {
            int len = 0;
            for (int l = 0; l < L_; l++) len += mask[b*L_ + l];
            ish[0] = len;
        }
    }
    __syncthreads();

    // Gram G = R R^T : 64 tiles (4x4) x 4 K-slices = 256 threads
    {
        int tile = tid & 63, ksl = tid >> 6;
        int q0 = (tile >> 3) * 4, k0 = (tile & 7) * 4;
        float acc[4][4] = {};
        for (int c4 = ksl*32; c4 < ksl*32 + 32; c4++) {
            float4 a[4], bb[4];
            #pragma unroll
            for (int i = 0; i < 4; i++) a[i]  = *(const float4*)&rsm[(q0+i)*516 + c4*4];
            #pragma unroll
            for (int j = 0; j < 4; j++) bb[j] = *(const float4*)&rsm[(k0+j)*516 + c4*4];
            #pragma unroll
            for (int i = 0; i < 4; i++)
                #pragma unroll
                for (int j = 0; j < 4; j++)
                    acc[i][j] += a[i].x*bb[j].x + a[i].y*bb[j].y
                               + a[i].z*bb[j].z + a[i].w*bb[j].w;
        }
        #pragma unroll
        for (int i = 0; i < 4; i++)
            #pragma unroll
            for (int j = 0; j < 4; j++)
                Gp[ksl*1024 + (q0+i)*32 + k0+j] = acc[i][j];
    }
    __syncthreads();
    {   // reduce 4 K-slices (float4 per thread)
        float4 s0 = *(float4*)&Gp[tid*4];
        float4 s1 = *(float4*)&Gp[1024 + tid*4];
        float4 s2 = *(float4*)&Gp[2048 + tid*4];
        float4 s3 = *(float4*)&Gp[3072 + tid*4];
        float4 r;
        r.x = s0.x+s1.x+s2.x+s3.x; r.y = s0.y+s1.y+s2.y+s3.y;
        r.z = s0.z+s1.z+s2.z+s3.z; r.w = s0.w+s1.w+s2.w+s3.w;
        *(float4*)&G[tid*4] = r;
    }
    __syncthreads();

    // credibility chain (keyt = Xb .* right  =>  scores_i = G .* Xb)
    if (tid < 32) {
        int q = tid;
        int   len   = ish[0];
        float len_f = (float)len;
        Xb[q] = (q < 30) ? 1.0f : 0.0f;
        __syncwarp();
        for (int it = 0; it < ITER_; it++) {
            float sc = inv_sqrt_d * scales_blk[it];
            if (q < 30) {
                float cr = 0.f;
                for (int k = 0; k < len; k++) cr += G[q*32 + k] * Xb[k];
                cred[q] = cr * sc / len_f;
            }
            __syncwarp();
            float xb = 0.f;
            if (q < 30) {
                float y = b_o[it*L_ + q];
                for (int j = 0; j < 30; j++) y += W_o[it*900 + q*30 + j] * cred[j];
                xb = tanhf(expf(y));
            }
            __syncwarp();
            if (q < 30) Xb[q] = xb;
            __syncwarp();
        }
        if (q < 30) {
            float sc = inv_sqrt_d * scale_fin[0];
            float e0 = b_c[0], e1 = b_c[1], e2 = b_c[2], e3 = b_c[3];
            for (int k = 0; k < 30; k++) {
                float s = G[q*32 + k] * Xb[k] * sc;
                e0 += s * W_c[k]; e1 += s * W_c[30+k]; e2 += s * W_c[60+k]; e3 += s * W_c[90+k];
            }
            evd[q*4+0] = tanhf(expf(e0)); evd[q*4+1] = tanhf(expf(e1));
            evd[q*4+2] = tanhf(expf(e2)); evd[q*4+3] = tanhf(expf(e3));
        }
    }
    __syncthreads();

    // lin = sum of 16 N-chunk partials, masked
    if (tid < 120) {
        int l = tid >> 2, h = tid & 3;
        int row = b*L_ + l;
        float s = 0.f;
        #pragma unroll
        for (int c = 0; c < NCHUNK_; c++)
            s += g_linpart[((size_t)c*ROWS_ + row)*4 + h];
        if (mask[row] == 0) s = -INFINITY;
        lin[l*4 + h] = s;
    }
    __syncthreads();

    // softmax over l (per h)
    if (tid < 4) {
        int h = tid;
        float m = -INFINITY;
        for (int l = 0; l < 30; l++) m = fmaxf(m, lin[l*4 + h]);
        float ssum = 0.f;
        for (int l = 0; l < 30; l++) { float e = expf(lin[l*4+h] - m); aw[l*4+h] = e; ssum += e; }
        float r = 1.f / ssum;
        for (int l = 0; l < 30; l++) aw[l*4 + h] *= r;
    }
    __syncthreads();

    // AOA GLU + write out2 = [evd | aw2]
    if (tid < 30) {
        int l = tid;
        float cat[8];
        #pragma unroll
        for (int h = 0; h < 4; h++) { cat[h] = aw[l*4+h]; cat[4+h] = evd[l*4+h]; }
        float g8[8];
        #pragma unroll
        for (int j = 0; j < 8; j++) {
            float s = b_aoa[j];
            #pragma unroll
            for (int m2 = 0; m2 < 8; m2++) s += W_aoa[j*8 + m2] * cat[m2];
            g8[j] = s;
        }
        size_t o2 = (size_t)B_*D_*H_ + (size_t)b*L_*8 + (size_t)l*8;
        #pragma unroll
        for (int h = 0; h < 4; h++) {
            float a2 = g8[h] * (1.f / (1.f + expf(-g8[4+h])));
            aw2[l*4 + h] = a2;
            out[o2 + h]     = evd[l*4 + h];
            out[o2 + 4 + h] = a2;
        }
    }
    __syncthreads();

    // attended[b,d,h] = sum_l right[b,l,d] * aw2[l,h]
    for (int d = tid; d < 512; d += 256) {
        float a0 = 0.f, a1 = 0.f, a2 = 0.f, a3 = 0.f;
        for (int l = 0; l < 30; l++) {
            float r = rsm[l*516 + d];
            a0 += r * aw2[l*4+0]; a1 += r * aw2[l*4+1];
            a2 += r * aw2[l*4+2]; a3 += r * aw2[l*4+3];
        }
        size_t o1 = (size_t)b*D_*H_ + (size_t)d*H_;
        out[o1+0] = a0; out[o1+1] = a1; out[o1+2] = a2; out[o1+3] = a3;
    }
}

// ---------------------------------------------------------------------------
extern "C" void kernel_launch(void* const* d_in, const int* in_sizes, int n_in,
                              void* d_out, int out_size)
{
    const float* left   = (const float*)d_in[0];
    const float* right  = (const float*)d_in[1];
    const int*   mask   = (const int*)  d_in[2];
    const float* W1     = (const float*)d_in[3];
    const float* W2     = (const float*)d_in[4];
    const float* W_o    = (const float*)d_in[5];
    const float* b_o    = (const float*)d_in[6];
    const float* scales = (const float*)d_in[7];
    const float* W_c    = (const float*)d_in[8];
    const float* b_c    = (const float*)d_in[9];
    const float* s_fin  = (const float*)d_in[10];
    const float* W_aoa  = (const float*)d_in[11];
    const float* b_aoa  = (const float*)d_in[12];
    float* out = (float*)d_out;

    const int smem3 = (32*516 + 4096 + 1024 + 32 + 32 + 4*128 + 8) * (int)sizeof(float);
    cudaFuncSetAttribute(k3_fused, cudaFuncAttributeMaxDynamicSharedMemorySize, smem3);

    uint32_t *dAh, *dAl, *dBh, *dBl;
    cudaGetSymbolAddress((void**)&dAh, g_Ah);
    cudaGetSymbolAddress((void**)&dAl, g_Al);
    cudaGetSymbolAddress((void**)&dBh, g_Bh);
    cudaGetSymbolAddress((void**)&dBl, g_Bl);

    // K0: preconvert right (dense) and W1-right (strided) to bf16 hi/lo
    long a4 = (long)ROWS_ * 128;           // 7,864,320 float4
    k0_convert<<<(unsigned)((a4 + 255) / 256), 256>>>(right, 512, 0, 128, a4, dAh, dAl);
    long b4 = 512L * 128;                  // 65,536 float4
    k0_convert<<<(unsigned)((b4 + 255) / 256), 256>>>(W1, 1024, 512, 128, b4, dBh, dBl);

    dim3 g1(2048/64, 512/64);      // 32 x 8
    k1_qgemm<<<g1, 256>>>(left, W1);

    dim3 g2(ROWS_/128, 512/64);    // 480 x 8
    k2_mma<<<g2, 256>>>(W2);

    k3_fused<<<B_, 256, smem3>>>(right, mask, W_o, b_o, scales,
                                 W_c, b_c, s_fin, W_aoa, b_aoa, out);
}